// round 2
// baseline (speedup 1.0000x reference)
#include <cuda_runtime.h>

#define HID 128
#define NMAX 50000

// Scratch (static __device__ — no allocations allowed)
__device__ float g_dinv[NMAX];
__device__ float g_hws[(size_t)NMAX * HID];
__device__ float g_agg[(size_t)NMAX * HID];
__device__ float g_h  [(size_t)NMAX * HID];
__device__ int   g_mode;   // 1 => edge_index is int64, 0 => int32

// ---------------------------------------------------------------------------
// Detect edge_index dtype: if the first 128 entries interpreted as int64 are
// all in [0, n), the buffer is genuinely int64 (int32 data read as int64 packs
// two random node ids -> value >= 2^32 almost surely).
__global__ void k_detect(const void* __restrict__ ei, int n) {
    const long long* p = (const long long*)ei;
    int ok = 1;
    for (int i = threadIdx.x; i < 128; i += 32) {
        long long v = p[i];
        if (v < 0 || v >= (long long)n) ok = 0;
    }
    ok = __all_sync(0xffffffffu, ok);
    if (threadIdx.x == 0) g_mode = ok;
}

// ---------------------------------------------------------------------------
// Degree (with self loop) -> dinv = rsqrt(deg)
__global__ void k_deg_init(int n) {
    int i = blockIdx.x * blockDim.x + threadIdx.x;
    if (i < n) g_dinv[i] = 1.0f;   // self loop contributes 1
}

__global__ void k_deg_edges(const void* __restrict__ ei, int E) {
    int e = blockIdx.x * blockDim.x + threadIdx.x;
    if (e >= E) return;
    int d;
    if (g_mode) d = (int)((const long long*)ei)[(size_t)E + e];
    else        d = ((const int*)ei)[(size_t)E + e];
    atomicAdd(&g_dinv[d], 1.0f);
}

__global__ void k_rsqrt(int n) {
    int i = blockIdx.x * blockDim.x + threadIdx.x;
    if (i < n) g_dinv[i] = rsqrtf(g_dinv[i]);
}

// ---------------------------------------------------------------------------
// GEMM: hws = (h @ W) * dinv[row]; also initializes agg = hws (self-loop term).
// Block: 256 threads (32x8), 32 rows x 128 cols per block. Thread computes 4x4.
// Shared: full W (64KB) + 32 h rows (16KB) = 80KB dynamic.
__global__ void k_gemm(const float* __restrict__ h, const float* __restrict__ W, int n) {
    extern __shared__ float sm[];
    float4* sW4 = (float4*)sm;            // 128x128 floats = 4096 float4
    float*  sh  = sm + HID * HID;         // 32x128 floats
    int tx = threadIdx.x, ty = threadIdx.y;
    int tid = ty * 32 + tx;
    int row0 = blockIdx.x * 32;

    const float4* W4 = (const float4*)W;
    #pragma unroll
    for (int i = tid; i < HID * HID / 4; i += 256) sW4[i] = W4[i];

    const float4* h4 = (const float4*)h;
    float4* sh4 = (float4*)sh;
    for (int i = tid; i < 32 * (HID / 4); i += 256) {
        int r = row0 + (i >> 5);
        sh4[i] = (r < n) ? h4[(size_t)r * (HID / 4) + (i & 31)]
                         : make_float4(0.f, 0.f, 0.f, 0.f);
    }
    __syncthreads();

    float acc[4][4];
    #pragma unroll
    for (int a = 0; a < 4; a++)
        #pragma unroll
        for (int b = 0; b < 4; b++) acc[a][b] = 0.f;

    #pragma unroll 4
    for (int k = 0; k < HID; k++) {
        float4 w = sW4[k * (HID / 4) + tx];
        #pragma unroll
        for (int rr = 0; rr < 4; rr++) {
            float hv = sh[(ty * 4 + rr) * HID + k];
            acc[rr][0] = fmaf(hv, w.x, acc[rr][0]);
            acc[rr][1] = fmaf(hv, w.y, acc[rr][1]);
            acc[rr][2] = fmaf(hv, w.z, acc[rr][2]);
            acc[rr][3] = fmaf(hv, w.w, acc[rr][3]);
        }
    }

    #pragma unroll
    for (int rr = 0; rr < 4; rr++) {
        int r = row0 + ty * 4 + rr;
        if (r < n) {
            float dv = g_dinv[r];
            float4 o = make_float4(acc[rr][0] * dv, acc[rr][1] * dv,
                                   acc[rr][2] * dv, acc[rr][3] * dv);
            ((float4*)g_hws)[(size_t)r * (HID / 4) + tx] = o;
            ((float4*)g_agg)[(size_t)r * (HID / 4) + tx] = o;   // self-loop init
        }
    }
}

// ---------------------------------------------------------------------------
// Edge scatter: one warp per edge; agg[dst] += hws[src]
// (hws already carries dinv[src]; the dinv[dst] factor is applied once, in
//  k_finalize — multiplying here as well was the R1 bug.)
__global__ void k_scatter(const void* __restrict__ ei, int E) {
    int gid = blockIdx.x * blockDim.x + threadIdx.x;
    int e = gid >> 5;
    int lane = gid & 31;
    if (e >= E) return;
    int s, d;
    if (g_mode) {
        const long long* p = (const long long*)ei;
        s = (int)p[e]; d = (int)p[(size_t)E + e];
    } else {
        const int* p = (const int*)ei;
        s = p[e]; d = p[(size_t)E + e];
    }
    float4 v = ((const float4*)g_hws)[(size_t)s * (HID / 4) + lane];
    float* a = g_agg + (size_t)d * HID + lane * 4;
    atomicAdd(a + 0, v.x);
    atomicAdd(a + 1, v.y);
    atomicAdd(a + 2, v.z);
    atomicAdd(a + 3, v.w);
}

// ---------------------------------------------------------------------------
// out = relu(agg * dinv[row] + bias)
__global__ void k_finalize(const float* __restrict__ b, float* __restrict__ out, int n) {
    int i = blockIdx.x * blockDim.x + threadIdx.x;   // float4 index
    if (i >= n * (HID / 4)) return;
    int r = i >> 5;
    int c = i & 31;
    float dv = g_dinv[r];
    float4 a  = ((const float4*)g_agg)[i];
    float4 bb = ((const float4*)b)[c];
    float4 o;
    o.x = fmaxf(fmaf(a.x, dv, bb.x), 0.f);
    o.y = fmaxf(fmaf(a.y, dv, bb.y), 0.f);
    o.z = fmaxf(fmaf(a.z, dv, bb.z), 0.f);
    o.w = fmaxf(fmaf(a.w, dv, bb.w), 0.f);
    ((float4*)out)[i] = o;
}

// ---------------------------------------------------------------------------
extern "C" void kernel_launch(void* const* d_in, const int* in_sizes, int n_in,
                              void* d_out, int out_size) {
    const float* x  = (const float*)d_in[0];
    const void*  ei = d_in[1];
    const float* Ws[3] = {(const float*)d_in[2], (const float*)d_in[4], (const float*)d_in[6]};
    const float* bs[3] = {(const float*)d_in[3], (const float*)d_in[5], (const float*)d_in[7]};
    int n = in_sizes[0] / HID;
    int E = in_sizes[1] / 2;

    const int smem = (HID * HID + 32 * HID) * 4;   // 80 KB
    cudaFuncSetAttribute(k_gemm, cudaFuncAttributeMaxDynamicSharedMemorySize, smem);

    float* gh = nullptr;
    cudaGetSymbolAddress((void**)&gh, g_h);

    const int tb = 256;
    k_detect<<<1, 32>>>(ei, n);
    k_deg_init<<<(n + tb - 1) / tb, tb>>>(n);
    k_deg_edges<<<(E + tb - 1) / tb, tb>>>(ei, E);
    k_rsqrt<<<(n + tb - 1) / tb, tb>>>(n);

    const float* hin = x;
    for (int l = 0; l < 3; l++) {
        k_gemm<<<(n + 31) / 32, dim3(32, 8), smem>>>(hin, Ws[l], n);
        long long tot = (long long)E * 32;
        int blocks = (int)((tot + tb - 1) / tb);
        k_scatter<<<blocks, tb>>>(ei, E);
        float* out = (l == 2) ? (float*)d_out : gh;
        k_finalize<<<(n * (HID / 4) + tb - 1) / tb, tb>>>(bs[l], out, n);
        hin = gh;
    }
}

// round 5
// speedup vs baseline: 2.3581x; 2.3581x over previous
#include <cuda_runtime.h>

#define HID 128
#define NMAX 50000
#define EMAX 600000

// Scratch (static __device__ — no allocations allowed)
__device__ float g_dinv[NMAX];
__device__ float g_hws[(size_t)NMAX * HID];
__device__ float g_h  [(size_t)NMAX * HID];
__device__ int   g_deg[NMAX];
__device__ int   g_rowptr[NMAX + 1];
__device__ int   g_cursor[NMAX];
__device__ int   g_col[EMAX];
__device__ int   g_bsum[128];
__device__ int   g_mode;   // 1 => edge_index is int64, 0 => int32

// ---------------------------------------------------------------------------
// Detect edge_index dtype (int32 data read as int64 -> huge values) + zero deg
__global__ void k_detect_zero(const void* __restrict__ ei, int n) {
    int i = blockIdx.x * blockDim.x + threadIdx.x;
    if (i < n) g_deg[i] = 0;
    if (blockIdx.x == 0 && threadIdx.x < 32) {
        const long long* p = (const long long*)ei;
        int ok = 1;
        for (int k = threadIdx.x; k < 128; k += 32) {
            long long v = p[k];
            if (v < 0 || v >= (long long)n) ok = 0;
        }
        ok = __all_sync(0xffffffffu, ok);
        if (threadIdx.x == 0) g_mode = ok;
    }
}

__global__ void k_hist(const void* __restrict__ ei, int E) {
    int e = blockIdx.x * blockDim.x + threadIdx.x;
    if (e >= E) return;
    int d;
    if (g_mode) d = (int)((const long long*)ei)[(size_t)E + e];
    else        d = ((const int*)ei)[(size_t)E + e];
    atomicAdd(&g_deg[d], 1);
}

// 3-phase exclusive scan of g_deg[0..n) into g_rowptr
__global__ void k_scan1(int n) {           // 1024 thr/block
    __shared__ int s[1024];
    int i = blockIdx.x * 1024 + threadIdx.x;
    int v = (i < n) ? g_deg[i] : 0;
    s[threadIdx.x] = v;
    __syncthreads();
    int acc = v;
    #pragma unroll
    for (int off = 1; off < 1024; off <<= 1) {
        int t = (threadIdx.x >= off) ? s[threadIdx.x - off] : 0;
        __syncthreads();
        acc += t;
        s[threadIdx.x] = acc;
        __syncthreads();
    }
    if (i < n) g_rowptr[i] = acc - v;      // exclusive (pre-offset)
    if (threadIdx.x == 1023) g_bsum[blockIdx.x] = acc;
}

__global__ void k_scan2(int nb) {          // 1 block, <=128 sums
    __shared__ int s[128];
    int v = (threadIdx.x < nb) ? g_bsum[threadIdx.x] : 0;
    s[threadIdx.x] = v;
    __syncthreads();
    int acc = v;
    #pragma unroll
    for (int off = 1; off < 128; off <<= 1) {
        int t = (threadIdx.x >= off) ? s[threadIdx.x - off] : 0;
        __syncthreads();
        acc += t;
        s[threadIdx.x] = acc;
        __syncthreads();
    }
    if (threadIdx.x < nb) g_bsum[threadIdx.x] = acc - v;   // exclusive
}

__global__ void k_scan3(int n, int E) {    // add offsets; cursor copy; dinv
    int i = blockIdx.x * blockDim.x + threadIdx.x;
    if (i < n) {
        int r = g_rowptr[i] + g_bsum[i >> 10];
        g_rowptr[i] = r;
        g_cursor[i] = r;
        g_dinv[i] = rsqrtf((float)(g_deg[i] + 1));  // +1 self loop
    }
    if (i == 0) g_rowptr[n] = E;
}

__global__ void k_fill(const void* __restrict__ ei, int E) {
    int e = blockIdx.x * blockDim.x + threadIdx.x;
    if (e >= E) return;
    int s, d;
    if (g_mode) {
        const long long* p = (const long long*)ei;
        s = (int)p[e]; d = (int)p[(size_t)E + e];
    } else {
        const int* p = (const int*)ei;
        s = p[e]; d = p[(size_t)E + e];
    }
    int pos = atomicAdd(&g_cursor[d], 1);
    g_col[pos] = s;
}

// ---------------------------------------------------------------------------
// GEMM: hws = (h @ W) * dinv[row]
__global__ void k_gemm(const float* __restrict__ h, const float* __restrict__ W, int n) {
    extern __shared__ float sm[];
    float4* sW4 = (float4*)sm;            // 128x128 floats
    float*  sh  = sm + HID * HID;         // 32x128 floats
    int tx = threadIdx.x, ty = threadIdx.y;
    int tid = ty * 32 + tx;
    int row0 = blockIdx.x * 32;

    const float4* W4 = (const float4*)W;
    #pragma unroll
    for (int i = tid; i < HID * HID / 4; i += 256) sW4[i] = W4[i];

    const float4* h4 = (const float4*)h;
    float4* sh4 = (float4*)sh;
    for (int i = tid; i < 32 * (HID / 4); i += 256) {
        int r = row0 + (i >> 5);
        sh4[i] = (r < n) ? h4[(size_t)r * (HID / 4) + (i & 31)]
                         : make_float4(0.f, 0.f, 0.f, 0.f);
    }
    __syncthreads();

    float acc[4][4];
    #pragma unroll
    for (int a = 0; a < 4; a++)
        #pragma unroll
        for (int b = 0; b < 4; b++) acc[a][b] = 0.f;

    #pragma unroll 4
    for (int k = 0; k < HID; k++) {
        float4 w = sW4[k * (HID / 4) + tx];
        #pragma unroll
        for (int rr = 0; rr < 4; rr++) {
            float hv = sh[(ty * 4 + rr) * HID + k];
            acc[rr][0] = fmaf(hv, w.x, acc[rr][0]);
            acc[rr][1] = fmaf(hv, w.y, acc[rr][1]);
            acc[rr][2] = fmaf(hv, w.z, acc[rr][2]);
            acc[rr][3] = fmaf(hv, w.w, acc[rr][3]);
        }
    }

    #pragma unroll
    for (int rr = 0; rr < 4; rr++) {
        int r = row0 + ty * 4 + rr;
        if (r < n) {
            float dv = g_dinv[r];
            float4 o = make_float4(acc[rr][0] * dv, acc[rr][1] * dv,
                                   acc[rr][2] * dv, acc[rr][3] * dv);
            ((float4*)g_hws)[(size_t)r * (HID / 4) + tx] = o;
        }
    }
}

// ---------------------------------------------------------------------------
// Gather-aggregate + finalize: one warp per dst node.
// out[v] = relu( (hws[v] + sum_{s in N(v)} hws[s]) * dinv[v] + b )
__global__ void k_agg(const float* __restrict__ b, float* __restrict__ out, int n) {
    int warp = (blockIdx.x * blockDim.x + threadIdx.x) >> 5;
    int lane = threadIdx.x & 31;
    if (warp >= n) return;
    int beg = g_rowptr[warp], end = g_rowptr[warp + 1];

    const float4* hws4 = (const float4*)g_hws;
    float4 sum = hws4[(size_t)warp * 32 + lane];   // self loop

    for (int base = beg; base < end; base += 32) {
        int m = end - base; if (m > 32) m = 32;
        int idx = (lane < m) ? g_col[base + lane] : 0;
        for (int k = 0; k < m; k++) {
            int s = __shfl_sync(0xffffffffu, idx, k);
            float4 v = hws4[(size_t)s * 32 + lane];
            sum.x += v.x; sum.y += v.y; sum.z += v.z; sum.w += v.w;
        }
    }

    float dv = g_dinv[warp];
    float4 bb = ((const float4*)b)[lane];
    float4 o;
    o.x = fmaxf(fmaf(sum.x, dv, bb.x), 0.f);
    o.y = fmaxf(fmaf(sum.y, dv, bb.y), 0.f);
    o.z = fmaxf(fmaf(sum.z, dv, bb.z), 0.f);
    o.w = fmaxf(fmaf(sum.w, dv, bb.w), 0.f);
    ((float4*)out)[(size_t)warp * 32 + lane] = o;
}

// ---------------------------------------------------------------------------
extern "C" void kernel_launch(void* const* d_in, const int* in_sizes, int n_in,
                              void* d_out, int out_size) {
    const float* x  = (const float*)d_in[0];
    const void*  ei = d_in[1];
    const float* Ws[3] = {(const float*)d_in[2], (const float*)d_in[4], (const float*)d_in[6]};
    const float* bs[3] = {(const float*)d_in[3], (const float*)d_in[5], (const float*)d_in[7]};
    int n = in_sizes[0] / HID;
    int E = in_sizes[1] / 2;

    const int smem = (HID * HID + 32 * HID) * 4;   // 80 KB
    cudaFuncSetAttribute(k_gemm, cudaFuncAttributeMaxDynamicSharedMemorySize, smem);

    float* gh = nullptr;
    cudaGetSymbolAddress((void**)&gh, g_h);

    const int tb = 256;
    int nb_scan = (n + 1023) / 1024;

    k_detect_zero<<<(n + tb - 1) / tb, tb>>>(ei, n);
    k_hist<<<(E + tb - 1) / tb, tb>>>(ei, E);
    k_scan1<<<nb_scan, 1024>>>(n);
    k_scan2<<<1, 128>>>(nb_scan);
    k_scan3<<<(n + tb - 1) / tb, tb>>>(n, E);
    k_fill<<<(E + tb - 1) / tb, tb>>>(ei, E);

    const float* hin = x;
    for (int l = 0; l < 3; l++) {
        k_gemm<<<(n + 31) / 32, dim3(32, 8), smem>>>(hin, Ws[l], n);
        float* out = (l == 2) ? (float*)d_out : gh;
        k_agg<<<(n * 32 + tb - 1) / tb, tb>>>(bs[l], out, n);
        hin = gh;
    }
}

// round 6
// speedup vs baseline: 2.6897x; 1.1406x over previous
#include <cuda_runtime.h>

#define HID 128
#define NMAX 50000
#define EMAX 600000

// Scratch (static __device__ — no allocations allowed)
__device__ float g_dinv[NMAX];
__device__ float g_hws[(size_t)NMAX * HID];
__device__ float g_h  [(size_t)NMAX * HID];
__device__ int   g_deg[NMAX];
__device__ int   g_rowptr[NMAX + 1];
__device__ int   g_cursor[NMAX];
__device__ int   g_col[EMAX];
__device__ int   g_bsum[128];
__device__ int   g_mode;   // 1 => edge_index is int64, 0 => int32

// ---------------------------------------------------------------------------
// Detect edge_index dtype (int32 data read as int64 -> huge values) + zero deg
__global__ void k_detect_zero(const void* __restrict__ ei, int n) {
    int i = blockIdx.x * blockDim.x + threadIdx.x;
    if (i < n) g_deg[i] = 0;
    if (blockIdx.x == 0 && threadIdx.x < 32) {
        const long long* p = (const long long*)ei;
        int ok = 1;
        for (int k = threadIdx.x; k < 128; k += 32) {
            long long v = p[k];
            if (v < 0 || v >= (long long)n) ok = 0;
        }
        ok = __all_sync(0xffffffffu, ok);
        if (threadIdx.x == 0) g_mode = ok;
    }
}

__global__ void k_hist(const void* __restrict__ ei, int E) {
    int e = blockIdx.x * blockDim.x + threadIdx.x;
    if (e >= E) return;
    int d;
    if (g_mode) d = (int)((const long long*)ei)[(size_t)E + e];
    else        d = ((const int*)ei)[(size_t)E + e];
    atomicAdd(&g_deg[d], 1);
}

// Block-level exclusive scan of g_deg -> g_rowptr (pre-offset) + block sums
__global__ void k_scan1(int n) {           // 1024 thr/block
    __shared__ int s[1024];
    int i = blockIdx.x * 1024 + threadIdx.x;
    int v = (i < n) ? g_deg[i] : 0;
    s[threadIdx.x] = v;
    __syncthreads();
    int acc = v;
    #pragma unroll
    for (int off = 1; off < 1024; off <<= 1) {
        int t = (threadIdx.x >= off) ? s[threadIdx.x - off] : 0;
        __syncthreads();
        acc += t;
        s[threadIdx.x] = acc;
        __syncthreads();
    }
    if (i < n) g_rowptr[i] = acc - v;      // exclusive (pre-offset)
    if (threadIdx.x == 1023) g_bsum[blockIdx.x] = acc;
}

// Fused: redundantly scan block sums (<=128 of them), apply offsets, cursor, dinv
__global__ void k_scan3(int n, int E, int nb) {
    __shared__ int s[129];
    if (threadIdx.x == 0) {
        int acc = 0;
        for (int k = 0; k < nb; k++) { s[k] = acc; acc += g_bsum[k]; }
    }
    __syncthreads();
    int i = blockIdx.x * blockDim.x + threadIdx.x;
    if (i < n) {
        int r = g_rowptr[i] + s[i >> 10];
        g_rowptr[i] = r;
        g_cursor[i] = r;
        g_dinv[i] = rsqrtf((float)(g_deg[i] + 1));  // +1 self loop
    }
    if (i == 0) g_rowptr[n] = E;
}

__global__ void k_fill(const void* __restrict__ ei, int E) {
    int e = blockIdx.x * blockDim.x + threadIdx.x;
    if (e >= E) return;
    int s, d;
    if (g_mode) {
        const long long* p = (const long long*)ei;
        s = (int)p[e]; d = (int)p[(size_t)E + e];
    } else {
        const int* p = (const int*)ei;
        s = p[e]; d = p[(size_t)E + e];
    }
    int pos = atomicAdd(&g_cursor[d], 1);
    g_col[pos] = s;
}

// ---------------------------------------------------------------------------
// GEMM: hws = (h @ W) * dinv[row]
// 64 rows x 128 cols per block, 256 threads (32x8), 8x4 outputs per thread.
// k-loop vectorized by 4 (float4 h row chunks): 128 FMA per 12 LDS per step.
// Shared: W 64KB + 64x128 h = 32KB -> 96KB dynamic.
__global__ void k_gemm(const float* __restrict__ h, const float* __restrict__ W, int n) {
    extern __shared__ float sm[];
    float4* sW4 = (float4*)sm;            // [128][32] float4
    float4* sh4 = (float4*)(sm + HID * HID);  // [64][32] float4
    int tx = threadIdx.x, ty = threadIdx.y;
    int tid = ty * 32 + tx;
    int row0 = blockIdx.x * 64;

    const float4* W4 = (const float4*)W;
    #pragma unroll
    for (int i = tid; i < HID * HID / 4; i += 256) sW4[i] = W4[i];

    const float4* h4 = (const float4*)h;
    for (int i = tid; i < 64 * 32; i += 256) {
        int r = row0 + (i >> 5);
        sh4[i] = (r < n) ? h4[(size_t)r * 32 + (i & 31)]
                         : make_float4(0.f, 0.f, 0.f, 0.f);
    }
    __syncthreads();

    float4 acc[8];
    #pragma unroll
    for (int a = 0; a < 8; a++) acc[a] = make_float4(0.f, 0.f, 0.f, 0.f);

    #pragma unroll 2
    for (int k4 = 0; k4 < 32; k4++) {
        float4 w0 = sW4[(4 * k4 + 0) * 32 + tx];
        float4 w1 = sW4[(4 * k4 + 1) * 32 + tx];
        float4 w2 = sW4[(4 * k4 + 2) * 32 + tx];
        float4 w3 = sW4[(4 * k4 + 3) * 32 + tx];
        #pragma unroll
        for (int rr = 0; rr < 8; rr++) {
            float4 hv = sh4[(ty * 8 + rr) * 32 + k4];
            acc[rr].x = fmaf(hv.x, w0.x, acc[rr].x);
            acc[rr].y = fmaf(hv.x, w0.y, acc[rr].y);
            acc[rr].z = fmaf(hv.x, w0.z, acc[rr].z);
            acc[rr].w = fmaf(hv.x, w0.w, acc[rr].w);
            acc[rr].x = fmaf(hv.y, w1.x, acc[rr].x);
            acc[rr].y = fmaf(hv.y, w1.y, acc[rr].y);
            acc[rr].z = fmaf(hv.y, w1.z, acc[rr].z);
            acc[rr].w = fmaf(hv.y, w1.w, acc[rr].w);
            acc[rr].x = fmaf(hv.z, w2.x, acc[rr].x);
            acc[rr].y = fmaf(hv.z, w2.y, acc[rr].y);
            acc[rr].z = fmaf(hv.z, w2.z, acc[rr].z);
            acc[rr].w = fmaf(hv.z, w2.w, acc[rr].w);
            acc[rr].x = fmaf(hv.w, w3.x, acc[rr].x);
            acc[rr].y = fmaf(hv.w, w3.y, acc[rr].y);
            acc[rr].z = fmaf(hv.w, w3.z, acc[rr].z);
            acc[rr].w = fmaf(hv.w, w3.w, acc[rr].w);
        }
    }

    #pragma unroll
    for (int rr = 0; rr < 8; rr++) {
        int r = row0 + ty * 8 + rr;
        if (r < n) {
            float dv = g_dinv[r];
            float4 o = make_float4(acc[rr].x * dv, acc[rr].y * dv,
                                   acc[rr].z * dv, acc[rr].w * dv);
            ((float4*)g_hws)[(size_t)r * 32 + tx] = o;
        }
    }
}

// ---------------------------------------------------------------------------
// Gather-aggregate + finalize: one warp per dst node, 4 loads in flight.
// out[v] = relu( (hws[v] + sum_{s in N(v)} hws[s]) * dinv[v] + b )
__global__ void k_agg(const float* __restrict__ b, float* __restrict__ out, int n) {
    int warp = (blockIdx.x * blockDim.x + threadIdx.x) >> 5;
    int lane = threadIdx.x & 31;
    if (warp >= n) return;
    int beg = g_rowptr[warp], end = g_rowptr[warp + 1];

    const float4* hws4 = (const float4*)g_hws;
    float4 sum = hws4[(size_t)warp * 32 + lane];   // self loop

    for (int base = beg; base < end; base += 32) {
        int m = end - base; if (m > 32) m = 32;
        int idx = (lane < m) ? g_col[base + lane] : 0;
        int k = 0;
        for (; k + 4 <= m; k += 4) {
            int s0 = __shfl_sync(0xffffffffu, idx, k);
            int s1 = __shfl_sync(0xffffffffu, idx, k + 1);
            int s2 = __shfl_sync(0xffffffffu, idx, k + 2);
            int s3 = __shfl_sync(0xffffffffu, idx, k + 3);
            float4 v0 = hws4[(size_t)s0 * 32 + lane];
            float4 v1 = hws4[(size_t)s1 * 32 + lane];
            float4 v2 = hws4[(size_t)s2 * 32 + lane];
            float4 v3 = hws4[(size_t)s3 * 32 + lane];
            sum.x += (v0.x + v1.x) + (v2.x + v3.x);
            sum.y += (v0.y + v1.y) + (v2.y + v3.y);
            sum.z += (v0.z + v1.z) + (v2.z + v3.z);
            sum.w += (v0.w + v1.w) + (v2.w + v3.w);
        }
        for (; k < m; k++) {
            int s = __shfl_sync(0xffffffffu, idx, k);
            float4 v = hws4[(size_t)s * 32 + lane];
            sum.x += v.x; sum.y += v.y; sum.z += v.z; sum.w += v.w;
        }
    }

    float dv = g_dinv[warp];
    float4 bb = ((const float4*)b)[lane];
    float4 o;
    o.x = fmaxf(fmaf(sum.x, dv, bb.x), 0.f);
    o.y = fmaxf(fmaf(sum.y, dv, bb.y), 0.f);
    o.z = fmaxf(fmaf(sum.z, dv, bb.z), 0.f);
    o.w = fmaxf(fmaf(sum.w, dv, bb.w), 0.f);
    ((float4*)out)[(size_t)warp * 32 + lane] = o;
}

// ---------------------------------------------------------------------------
extern "C" void kernel_launch(void* const* d_in, const int* in_sizes, int n_in,
                              void* d_out, int out_size) {
    const float* x  = (const float*)d_in[0];
    const void*  ei = d_in[1];
    const float* Ws[3] = {(const float*)d_in[2], (const float*)d_in[4], (const float*)d_in[6]};
    const float* bs[3] = {(const float*)d_in[3], (const float*)d_in[5], (const float*)d_in[7]};
    int n = in_sizes[0] / HID;
    int E = in_sizes[1] / 2;

    const int smem = (HID * HID + 64 * HID) * 4;   // 96 KB
    cudaFuncSetAttribute(k_gemm, cudaFuncAttributeMaxDynamicSharedMemorySize, smem);

    float* gh = nullptr;
    cudaGetSymbolAddress((void**)&gh, g_h);

    const int tb = 256;
    int nb_scan = (n + 1023) / 1024;

    k_detect_zero<<<(n + tb - 1) / tb, tb>>>(ei, n);
    k_hist<<<(E + tb - 1) / tb, tb>>>(ei, E);
    k_scan1<<<nb_scan, 1024>>>(n);
    k_scan3<<<(n + tb - 1) / tb, tb>>>(n, E, nb_scan);
    k_fill<<<(E + tb - 1) / tb, tb>>>(ei, E);

    const float* hin = x;
    for (int l = 0; l < 3; l++) {
        k_gemm<<<(n + 63) / 64, dim3(32, 8), smem>>>(hin, Ws[l], n);
        float* out = (l == 2) ? (float*)d_out : gh;
        k_agg<<<(n * 32 + tb - 1) / tb, tb>>>(bs[l], out, n);
        hin = gh;
    }
}